// round 15
// baseline (speedup 1.0000x reference)
#include <cuda_runtime.h>
#include <cuda_fp16.h>
#include <math.h>
#include <stdint.h>

#define Bsz 2
#define T 2048
#define D 1024
#define NH 16
#define HD 64
#define NT (Bsz*T)    /* 4096 rows */
#define DFF 4096

// ---------------- scratch ----------------
__device__ half  g_q [NT*D];
__device__ half  g_k [NT*D];
__device__ half  g_v [NT*D];
__device__ float g_x2[NT*D];

__device__ half g_h  [NT*D];          // LN1 out
__device__ half g_a  [NT*D];          // attention out
__device__ half g_h2 [NT*D];          // LN2 out
__device__ half g_f1 [(size_t)NT*DFF];// FFN mid

__device__ half g_WqT[D*D];
__device__ half g_WkT[D*D];
__device__ half g_WvT[D*D];
__device__ half g_WoT[D*D];
__device__ half g_W1T[(size_t)D*DFF];   // [DFF, D]
__device__ half g_W2T[(size_t)D*DFF];   // [D, DFF]

// ---------------- helpers ----------------
__device__ __forceinline__ uint32_t s2u(const void* p) {
    uint32_t a;
    asm("{ .reg .u64 t; cvta.to.shared.u64 t, %1; cvt.u32.u64 %0, t; }" : "=r"(a) : "l"(p));
    return a;
}
__device__ __forceinline__ void cp16(uint32_t d, const void* s) {
    asm volatile("cp.async.cg.shared.global [%0], [%1], 16;" :: "r"(d), "l"(s));
}
__device__ __forceinline__ void ldm4(uint32_t* r, uint32_t addr) {
    asm volatile("ldmatrix.sync.aligned.m8n8.x4.shared.b16 {%0,%1,%2,%3}, [%4];"
        : "=r"(r[0]), "=r"(r[1]), "=r"(r[2]), "=r"(r[3]) : "r"(addr));
}
// fp16-accumulator HMMA: D(f16x2 x2) = A*B + C
__device__ __forceinline__ void mma_f16a(uint32_t* c, const uint32_t* a, const uint32_t* b) {
    asm volatile("mma.sync.aligned.m16n8k16.row.col.f16.f16.f16.f16 "
        "{%0,%1}, {%2,%3,%4,%5}, {%6,%7}, {%0,%1};"
        : "+r"(c[0]), "+r"(c[1])
        : "r"(a[0]), "r"(a[1]), "r"(a[2]), "r"(a[3]), "r"(b[0]), "r"(b[1]));
}

// ---------------- LayerNorm: one block per row, writes fp16 ----------------
__global__ void __launch_bounds__(256) ln_kernel(const float* __restrict__ x,
                                                 const float* __restrict__ gam,
                                                 const float* __restrict__ bet,
                                                 half* __restrict__ oh)
{
    int row = blockIdx.x;
    const float* xr = x + (size_t)row * D;
    int tid = threadIdx.x;

    float v[4];
    float s = 0.f, s2 = 0.f;
#pragma unroll
    for (int i = 0; i < 4; i++) {
        v[i] = xr[tid + i * 256];
        s  += v[i];
        s2 += v[i] * v[i];
    }
#pragma unroll
    for (int o = 16; o > 0; o >>= 1) {
        s  += __shfl_xor_sync(0xffffffffu, s,  o);
        s2 += __shfl_xor_sync(0xffffffffu, s2, o);
    }
    __shared__ float sh[2][8];
    int w = tid >> 5, l = tid & 31;
    if (l == 0) { sh[0][w] = s; sh[1][w] = s2; }
    __syncthreads();
    float ts = 0.f, ts2 = 0.f;
#pragma unroll
    for (int i = 0; i < 8; i++) { ts += sh[0][i]; ts2 += sh[1][i]; }
    float mean = ts * (1.0f / D);
    float var  = ts2 * (1.0f / D) - mean * mean;
    float inv  = rsqrtf(var + 1e-5f);
#pragma unroll
    for (int i = 0; i < 4; i++) {
        int idx = tid + i * 256;
        float vv = (v[i] - mean) * inv * gam[idx] + bet[idx];
        oh[(size_t)row * D + idx] = __float2half_rn(vv);
    }
}

// ---------------- transpose + convert: W[K,N] fp32 -> T [N,K] fp16 ----------------
__global__ void __launch_bounds__(256) tcvt_kernel(const float* __restrict__ W,
                                                   half* __restrict__ Th,
                                                   int K, int N)
{
    __shared__ float t[32][33];
    int n0 = blockIdx.x * 32, k0 = blockIdx.y * 32;
    int tx = threadIdx.x, ty = threadIdx.y;
#pragma unroll
    for (int j = 0; j < 4; j++)
        t[ty + j * 8][tx] = W[(size_t)(k0 + ty + j * 8) * N + n0 + tx];
    __syncthreads();
#pragma unroll
    for (int j = 0; j < 4; j++) {
        float v = t[tx][ty + j * 8];
        Th[(size_t)(n0 + ty + j * 8) * K + k0 + tx] = __float2half_rn(v);
    }
}

// fused 4x D x D transpose: blockIdx.z selects weight
__global__ void __launch_bounds__(256) tcvt4_kernel(
    const float* __restrict__ W0, half* __restrict__ T0,
    const float* __restrict__ W1, half* __restrict__ T1,
    const float* __restrict__ W2, half* __restrict__ T2,
    const float* __restrict__ W3, half* __restrict__ T3)
{
    const float* W = (blockIdx.z == 0) ? W0 : (blockIdx.z == 1) ? W1 : (blockIdx.z == 2) ? W2 : W3;
    half*       Th = (blockIdx.z == 0) ? T0 : (blockIdx.z == 1) ? T1 : (blockIdx.z == 2) ? T2 : T3;
    __shared__ float t[32][33];
    int n0 = blockIdx.x * 32, k0 = blockIdx.y * 32;
    int tx = threadIdx.x, ty = threadIdx.y;
#pragma unroll
    for (int j = 0; j < 4; j++)
        t[ty + j * 8][tx] = W[(size_t)(k0 + ty + j * 8) * D + n0 + tx];
    __syncthreads();
#pragma unroll
    for (int j = 0; j < 4; j++) {
        float v = t[tx][ty + j * 8];
        Th[(size_t)(n0 + ty + j * 8) * D + k0 + tx] = __float2half_rn(v);
    }
}

// ---------------- fp16 HMMA GEMM core (f16 acc, promoted to f32 every K=64) ----
// C = act(A @ B^T + bias) + res ; A [M,K] fp16, B [N,K] fp16.
// CTA 256x128, 8 warps 64x64, BK=32, 4-stage cp.async pipeline, 1 sync/chunk.
// stage: A 256x80B (20480) + B 128x80B (10240) = 30720 B.
#define STG 30720
#define MM_SMEM (4 * STG)

__device__ __forceinline__ void mm_body(
    const half* __restrict__ Ah, const half* __restrict__ Bh,
    const float* __restrict__ bias, const float* __restrict__ res,
    float* __restrict__ Cf, half* __restrict__ Ch,
    int K, int N, int gelu_flag, int bm, int bnc, char* smem)
{
    uint32_t sb = s2u(smem);
    int tid = threadIdx.x, warp = tid >> 5, lane = tid & 31;
    int wm = warp & 3, wn = warp >> 2;
    const int nchunk = K / 32;   // always even (32 or 128)

    int lr = tid >> 2;          // 0..63
    int cb = (tid & 3) * 16;    // byte chunk in a 64B k-slab

    auto load_stage = [&](int st, int c) {
        uint32_t base = sb + st * STG;
        size_t ko = (size_t)c * 64 + cb;
#pragma unroll
        for (int i = 0; i < 4; i++) {
            int r = lr + i * 64;
            cp16(base + r * 80 + cb, (const char*)Ah + ((size_t)(bm * 256 + r) * K) * 2 + ko);
        }
#pragma unroll
        for (int i = 0; i < 2; i++) {
            int r = lr + i * 64;
            cp16(base + 20480 + r * 80 + cb, (const char*)Bh + ((size_t)(bnc * 128 + r) * K) * 2 + ko);
        }
    };

    float acc[4][8][4];
#pragma unroll
    for (int i = 0; i < 4; i++)
#pragma unroll
        for (int j = 0; j < 8; j++)
#pragma unroll
            for (int r = 0; r < 4; r++) acc[i][j][r] = 0.f;

    load_stage(0, 0); asm volatile("cp.async.commit_group;" ::: "memory");
    load_stage(1, 1); asm volatile("cp.async.commit_group;" ::: "memory");
    load_stage(2, 2); asm volatile("cp.async.commit_group;" ::: "memory");

    int a_row = wm * 64 + (lane & 15);
    int a_kb  = (lane >> 4) * 16;
    int b_row = wn * 64 + (lane & 7) + ((lane >> 4) << 3);
    int b_kb  = ((lane >> 3) & 1) * 16;

    for (int it = 0; it < nchunk; it += 2) {
        uint32_t c16[4][8][2];
#pragma unroll
        for (int i = 0; i < 4; i++)
#pragma unroll
            for (int j = 0; j < 8; j++) { c16[i][j][0] = 0; c16[i][j][1] = 0; }

#pragma unroll
        for (int sub = 0; sub < 2; sub++) {
            int itc = it + sub;
            asm volatile("cp.async.wait_group 2;" ::: "memory");
            __syncthreads();
            // loads write stage (itc+3)&3; warps are <=1 iter apart -> disjoint
            if (itc + 3 < nchunk) load_stage((itc + 3) & 3, itc + 3);
            asm volatile("cp.async.commit_group;" ::: "memory");

            uint32_t stb = sb + (itc & 3) * STG;
#pragma unroll
            for (int ks = 0; ks < 2; ks++) {
                uint32_t aH[4][4];
#pragma unroll
                for (int mt = 0; mt < 4; mt++)
                    ldm4(aH[mt], stb + (a_row + mt * 16) * 80 + ks * 32 + a_kb);
#pragma unroll
                for (int np = 0; np < 4; np++) {
                    uint32_t bh[4];
                    ldm4(bh, stb + 20480 + (b_row + np * 16) * 80 + ks * 32 + b_kb);
#pragma unroll
                    for (int mt = 0; mt < 4; mt++) {
                        mma_f16a(c16[mt][np * 2],     aH[mt], bh);
                        mma_f16a(c16[mt][np * 2 + 1], aH[mt], bh + 2);
                    }
                }
            }
        }

        // promote fp16 group accumulators into fp32 master accumulators
#pragma unroll
        for (int mt = 0; mt < 4; mt++)
#pragma unroll
            for (int j = 0; j < 8; j++) {
                float2 f0 = __half22float2(*(__half2*)&c16[mt][j][0]);
                float2 f1 = __half22float2(*(__half2*)&c16[mt][j][1]);
                acc[mt][j][0] += f0.x; acc[mt][j][1] += f0.y;
                acc[mt][j][2] += f1.x; acc[mt][j][3] += f1.y;
            }
    }

    // ---- epilogue ----
    int qr = lane >> 2, qc = (lane & 3) * 2;
#pragma unroll
    for (int mt = 0; mt < 4; mt++) {
#pragma unroll
        for (int nt = 0; nt < 8; nt++) {
            int col = bnc * 128 + wn * 64 + nt * 8 + qc;
            float b0 = bias ? bias[col] : 0.f;
            float b1 = bias ? bias[col + 1] : 0.f;
#pragma unroll
            for (int hf = 0; hf < 2; hf++) {
                size_t row = (size_t)bm * 256 + wm * 64 + mt * 16 + qr + hf * 8;
                float v0 = acc[mt][nt][hf * 2]     + b0;
                float v1 = acc[mt][nt][hf * 2 + 1] + b1;
                if (gelu_flag) {
                    v0 = 0.5f * v0 * (1.0f + erff(v0 * 0.70710678118654752f));
                    v1 = 0.5f * v1 * (1.0f + erff(v1 * 0.70710678118654752f));
                }
                size_t idx = row * (size_t)N + col;
                if (res) { v0 += res[idx]; v1 += res[idx + 1]; }
                if (Cf) {
                    *(float2*)(Cf + idx) = make_float2(v0, v1);
                } else {
                    *(__half2*)(Ch + idx) = __halves2half2(__float2half_rn(v0), __float2half_rn(v1));
                }
            }
        }
    }
}

__global__ void __launch_bounds__(256, 1) mm_kernel(
    const half* __restrict__ Ah, const half* __restrict__ Bh,
    const float* __restrict__ bias, const float* __restrict__ res,
    float* __restrict__ Cf, half* __restrict__ Ch,
    int K, int N, int gelu_flag)
{
    extern __shared__ char smem[];
    mm_body(Ah, Bh, bias, res, Cf, Ch, K, N, gelu_flag, blockIdx.y, blockIdx.x, smem);
}

__global__ void __launch_bounds__(256, 1) qkv_kernel(
    const half* __restrict__ Ah,
    const half* __restrict__ Bq, half* __restrict__ Cq,
    const half* __restrict__ Bk, half* __restrict__ Ck,
    const half* __restrict__ Bv, half* __restrict__ Cv)
{
    extern __shared__ char smem[];
    int sel = blockIdx.x >> 3, bnc = blockIdx.x & 7;
    const half* Bh = (sel == 0) ? Bq : (sel == 1) ? Bk : Bv;
    half* Ch       = (sel == 0) ? Cq : (sel == 1) ? Ck : Cv;
    mm_body(Ah, Bh, nullptr, nullptr, nullptr, Ch, D, D, 0, blockIdx.y, bnc, smem);
}

// ---------------- Attention: smem-tiled half2, 64 queries per CTA ----------------
#define KS_OFF   0
#define VS_OFF   25344
#define K0_OFF   50688
#define V0_OFF   50816
#define PS_OFF   50944
#define ATTN_SMEM 56064

__global__ void __launch_bounds__(256, 1) attn_tile_kernel(
    const half* __restrict__ Q, const half* __restrict__ K,
    const half* __restrict__ V, half* __restrict__ O)
{
    extern __shared__ char smem[];
    __half2* Ks  = (__half2*)(smem + KS_OFF);   // [r*33 + d2]
    __half2* Vs  = (__half2*)(smem + VS_OFF);   // [r*33 + d2]
    __half2* k0s = (__half2*)(smem + K0_OFF);
    __half2* v0s = (__half2*)(smem + V0_OFF);
    float*   ps  = (float*)(smem + PS_OFF);     // [warp*160 + kk]

    int tid = threadIdx.x, warp = tid >> 5, lane = tid & 31;
    int q0 = blockIdx.x * 64;
    int h = blockIdx.y, b = blockIdx.z;
    size_t base = (size_t)b * T * D + h * HD;

    int kLo = q0 - 128; if (kLo < 0) kLo = 0;
    int R = q0 + 64 - kLo;                 // <= 192

    for (int idx = tid; idx < R * 32; idx += 256) {
        int r = idx >> 5, d = idx & 31;
        Ks[r * 33 + d] = ((const __half2*)(K + base + (size_t)(kLo + r) * D))[d];
        Vs[r * 33 + d] = ((const __half2*)(V + base + (size_t)(kLo + r) * D))[d];
    }
    if (tid < 32) {
        k0s[tid] = ((const __half2*)(K + base))[tid];
        v0s[tid] = ((const __half2*)(V + base))[tid];
    }
    __syncthreads();

    float* pw = ps + warp * 160;

    for (int qq = 0; qq < 8; qq++) {
        int i = q0 + warp * 8 + qq;
        if (i == T - 1) continue;   // dense row handled separately

        float qreg[64];
        const __half2* qp2 = (const __half2*)(Q + base + (size_t)i * D);
#pragma unroll
        for (int t = 0; t < 32; t++) {
            float2 f = __half22float2(qp2[t]);
            qreg[2 * t] = f.x; qreg[2 * t + 1] = f.y;
        }

        int jLo = i - 128; if (jLo < 0) jLo = 0;
        int nk = i - jLo + 1;          // <= 129
        int rBase = jLo - kLo;         // >= 0

        // phase 1: scores (lanes over keys)
        float sc[5];
        float mloc = -1e30f;
#pragma unroll
        for (int bq = 0; bq < 5; bq++) {
            int kk = lane + bq * 32;
            float s = -1e30f;
            if (kk < nk) {
                const __half2* kr = Ks + (rBase + kk) * 33;
                s = 0.f;
#pragma unroll
                for (int d = 0; d < 32; d++) {
                    float2 kv = __half22float2(kr[d]);
                    s += qreg[2 * d] * kv.x + qreg[2 * d + 1] * kv.y;
                }
                s *= 0.125f;
            }
            sc[bq] = s;
            mloc = fmaxf(mloc, s);
        }
        float s0 = -1e30f;
        if (jLo > 0) {                  // global key 0 outside window
            s0 = 0.f;
#pragma unroll
            for (int d = 0; d < 32; d++) {
                float2 kv = __half22float2(k0s[d]);
                s0 += qreg[2 * d] * kv.x + qreg[2 * d + 1] * kv.y;
            }
            s0 *= 0.125f;
            mloc = fmaxf(mloc, s0);
        }
#pragma unroll
        for (int o = 16; o > 0; o >>= 1) mloc = fmaxf(mloc, __shfl_xor_sync(0xffffffffu, mloc, o));

        float lloc = 0.f;
#pragma unroll
        for (int bq = 0; bq < 5; bq++) {
            float p = __expf(sc[bq] - mloc);
            pw[lane + bq * 32] = p;
            lloc += p;
        }
        float p0 = 0.f;
        if (jLo > 0) {
            p0 = __expf(s0 - mloc);
            if (lane == 0) lloc += p0;
        }
#pragma unroll
        for (int o = 16; o > 0; o >>= 1) lloc += __shfl_xor_sync(0xffffffffu, lloc, o);
        __syncwarp();

        // phase 2: output accumulation, lane owns dim pair (2*lane, 2*lane+1)
        float2 v0p = __half22float2(v0s[lane]);
        float o0 = (jLo > 0) ? p0 * v0p.x : 0.f;
        float o1 = (jLo > 0) ? p0 * v0p.y : 0.f;
        for (int kk = 0; kk < nk; kk += 4) {
            float4 p4 = *(float4*)(pw + kk);
            float pv[4] = {p4.x, p4.y, p4.z, p4.w};
#pragma unroll
            for (int t = 0; t < 4; t++) {
                int r = rBase + kk + t;
                if (r > R - 1) r = R - 1;       // p=0 there; clamp avoids OOB
                float2 v2 = __half22float2(Vs[r * 33 + lane]);
                o0 += pv[t] * v2.x;
                o1 += pv[t] * v2.y;
            }
        }
        float inv = 1.f / lloc;
        *(__half2*)(O + base + (size_t)i * D + 2 * lane) =
            __halves2half2(__float2half_rn(o0 * inv), __float2half_rn(o1 * inv));
        __syncwarp();
    }
}

// Dense row i = T-1: 8 warps partition keys (2-way unrolled), log-sum-exp merge.
__global__ void __launch_bounds__(256) attn_last_kernel(
    const half* __restrict__ Q, const half* __restrict__ K,
    const half* __restrict__ V, half* __restrict__ O)
{
    int lane = threadIdx.x & 31;
    int warp = threadIdx.x >> 5;
    int h = blockIdx.x, b = blockIdx.y;
    const int i = T - 1;

    size_t base = (size_t)b * T * D + h * HD;
    const half* qp = Q + base + (size_t)i * D;
    float q0 = __half2float(qp[lane]) * 0.125f, q1 = __half2float(qp[lane + 32]) * 0.125f;

    float m = -1e30f, l = 0.f, o0 = 0.f, o1 = 0.f;
    for (int j = warp; j < T; j += 16) {
        const half* kpa = K + base + (size_t)j * D;
        const half* kpb = kpa + (size_t)8 * D;
        float sa = q0 * __half2float(kpa[lane]) + q1 * __half2float(kpa[lane + 32]);
        float sb = q0 * __half2float(kpb[lane]) + q1 * __half2float(kpb[lane + 32]);
#pragma unroll
        for (int o = 16; o > 0; o >>= 1) {
            sa += __shfl_xor_sync(0xffffffffu, sa, o);
            sb += __shfl_xor_sync(0xffffffffu, sb, o);
        }
        float nm = fmaxf(m, fmaxf(sa, sb));
        float scx = __expf(m - nm);
        float pa = __expf(sa - nm);
        float pb = __expf(sb - nm);
        const half* vpa = V + base + (size_t)j * D;
        const half* vpb = vpa + (size_t)8 * D;
        l  = l  * scx + pa + pb;
        o0 = o0 * scx + pa * __half2float(vpa[lane]) + pb * __half2float(vpb[lane]);
        o1 = o1 * scx + pa * __half2float(vpa[lane + 32]) + pb * __half2float(vpb[lane + 32]);
        m = nm;
    }
    __shared__ float sm[8], sl[8], so[8][64];
    if (lane == 0) { sm[warp] = m; sl[warp] = l; }
    so[warp][lane] = o0; so[warp][lane + 32] = o1;
    __syncthreads();
    if (warp == 0) {
        float gm = -1e30f;
#pragma unroll
        for (int w = 0; w < 8; w++) gm = fmaxf(gm, sm[w]);
        float gl = 0.f, a0 = 0.f, a1 = 0.f;
#pragma unroll
        for (int w = 0; w < 8; w++) {
            float scx = __expf(sm[w] - gm);
            gl += scx * sl[w];
            a0 += scx * so[w][lane];
            a1 += scx * so[w][lane + 32];
        }
        float inv = 1.f / gl;
        size_t oidx = base + (size_t)i * D;
        O[oidx + lane]      = __float2half_rn(a0 * inv);
        O[oidx + lane + 32] = __float2half_rn(a1 * inv);
    }
}

// ---------------- launch ----------------
extern "C" void kernel_launch(void* const* d_in, const int* in_sizes, int n_in,
                              void* d_out, int out_size)
{
    const float* x    = (const float*)d_in[0];
    const float* ln1g = (const float*)d_in[1];
    const float* ln1b = (const float*)d_in[2];
    const float* ln2g = (const float*)d_in[3];
    const float* ln2b = (const float*)d_in[4];
    const float* Wq   = (const float*)d_in[5];
    const float* Wk   = (const float*)d_in[6];
    const float* Wv   = (const float*)d_in[7];
    const float* Wo   = (const float*)d_in[8];
    const float* bo   = (const float*)d_in[9];
    const float* W1   = (const float*)d_in[10];
    const float* b1   = (const float*)d_in[11];
    const float* W2   = (const float*)d_in[12];
    const float* b2   = (const float*)d_in[13];
    float* out = (float*)d_out;

    cudaFuncSetAttribute(mm_kernel,  cudaFuncAttributeMaxDynamicSharedMemorySize, MM_SMEM);
    cudaFuncSetAttribute(qkv_kernel, cudaFuncAttributeMaxDynamicSharedMemorySize, MM_SMEM);
    cudaFuncSetAttribute(attn_tile_kernel, cudaFuncAttributeMaxDynamicSharedMemorySize, ATTN_SMEM);

    half *q, *k, *v;
    float *x2;
    half *hA, *aA, *h2A, *f1A;
    half *WqT, *WkT, *WvT, *WoT, *W1T, *W2T;
    cudaGetSymbolAddress((void**)&q,   g_q);
    cudaGetSymbolAddress((void**)&k,   g_k);
    cudaGetSymbolAddress((void**)&v,   g_v);
    cudaGetSymbolAddress((void**)&x2,  g_x2);
    cudaGetSymbolAddress((void**)&hA,  g_h);
    cudaGetSymbolAddress((void**)&aA,  g_a);
    cudaGetSymbolAddress((void**)&h2A, g_h2);
    cudaGetSymbolAddress((void**)&f1A, g_f1);
    cudaGetSymbolAddress((void**)&WqT, g_WqT);
    cudaGetSymbolAddress((void**)&WkT, g_WkT);
    cudaGetSymbolAddress((void**)&WvT, g_WvT);
    cudaGetSymbolAddress((void**)&WoT, g_WoT);
    cudaGetSymbolAddress((void**)&W1T, g_W1T);
    cudaGetSymbolAddress((void**)&W2T, g_W2T);

    dim3 tb(32, 8);
    tcvt4_kernel<<<dim3(D / 32, D / 32, 4), tb>>>(Wq, WqT, Wk, WkT, Wv, WvT, Wo, WoT);
    tcvt_kernel<<<dim3(DFF / 32, D / 32), tb>>>(W1, W1T, D, DFF);
    tcvt_kernel<<<dim3(D / 32, DFF / 32), tb>>>(W2, W2T, DFF, D);

    // 1. h = LN1(x)
    ln_kernel<<<NT, 256>>>(x, ln1g, ln1b, hA);

    // 2. fused QKV (fp16 out)
    qkv_kernel<<<dim3(24, NT / 256), 256, MM_SMEM>>>(hA, WqT, q, WkT, k, WvT, v);

    // 3. attention
    attn_tile_kernel<<<dim3(T / 64, NH, Bsz), 256, ATTN_SMEM>>>(q, k, v, aA);
    attn_last_kernel<<<dim3(NH, Bsz), 256>>>(q, k, v, aA);

    // 4. x2 = x + att @ Wo + bo
    dim3 gD(D / 128, NT / 256);
    mm_kernel<<<gD, 256, MM_SMEM>>>(aA, WoT, bo, x, x2, nullptr, D, D, 0);

    // 5. h2 = LN2(x2)
    ln_kernel<<<NT, 256>>>(x2, ln2g, ln2b, h2A);

    // 6. f1 = gelu(h2 @ W1 + b1)
    dim3 gF(DFF / 128, NT / 256);
    mm_kernel<<<gF, 256, MM_SMEM>>>(h2A, W1T, b1, nullptr, nullptr, f1A, D, DFF, 1);

    // 7. out = x2 + f1 @ W2 + b2
    mm_kernel<<<gD, 256, MM_SMEM>>>(f1A, W2T, b2, x2, out, nullptr, DFF, D, 0);
}

// round 16
// speedup vs baseline: 1.1819x; 1.1819x over previous
#include <cuda_runtime.h>
#include <cuda_fp16.h>
#include <math.h>
#include <stdint.h>

#define Bsz 2
#define T 2048
#define D 1024
#define NH 16
#define HD 64
#define NT (Bsz*T)    /* 4096 rows */
#define DFF 4096

// ---------------- scratch ----------------
__device__ float g_q [NT*D];
__device__ float g_k [NT*D];
__device__ float g_v [NT*D];
__device__ float g_x2[NT*D];

__device__ half g_h  [NT*D];          // LN1 out
__device__ half g_a  [NT*D];          // attention out
__device__ half g_h2 [NT*D];          // LN2 out
__device__ half g_f1 [(size_t)NT*DFF];// FFN mid

__device__ half g_WqT[D*D];
__device__ half g_WkT[D*D];
__device__ half g_WvT[D*D];
__device__ half g_WoT[D*D];
__device__ half g_W1T[(size_t)D*DFF];   // [DFF, D]
__device__ half g_W2T[(size_t)D*DFF];   // [D, DFF]

// ---------------- helpers ----------------
__device__ __forceinline__ uint32_t s2u(const void* p) {
    uint32_t a;
    asm("{ .reg .u64 t; cvta.to.shared.u64 t, %1; cvt.u32.u64 %0, t; }" : "=r"(a) : "l"(p));
    return a;
}
__device__ __forceinline__ void cp16(uint32_t d, const void* s) {
    asm volatile("cp.async.cg.shared.global [%0], [%1], 16;" :: "r"(d), "l"(s));
}
__device__ __forceinline__ void ldm4(uint32_t* r, uint32_t addr) {
    asm volatile("ldmatrix.sync.aligned.m8n8.x4.shared.b16 {%0,%1,%2,%3}, [%4];"
        : "=r"(r[0]), "=r"(r[1]), "=r"(r[2]), "=r"(r[3]) : "r"(addr));
}
__device__ __forceinline__ void mma_fp16(float* d, const uint32_t* a, const uint32_t* b) {
    asm volatile("mma.sync.aligned.m16n8k16.row.col.f32.f16.f16.f32 "
        "{%0,%1,%2,%3}, {%4,%5,%6,%7}, {%8,%9}, {%0,%1,%2,%3};"
        : "+f"(d[0]), "+f"(d[1]), "+f"(d[2]), "+f"(d[3])
        : "r"(a[0]), "r"(a[1]), "r"(a[2]), "r"(a[3]), "r"(b[0]), "r"(b[1]));
}

// ---------------- LayerNorm: warp per row, float4, no block sync ----------------
__global__ void __launch_bounds__(256) ln_kernel(const float* __restrict__ x,
                                                 const float* __restrict__ gam,
                                                 const float* __restrict__ bet,
                                                 half* __restrict__ oh)
{
    int warp = threadIdx.x >> 5, lane = threadIdx.x & 31;
    int row = blockIdx.x * 8 + warp;
    const float4* xr = (const float4*)(x + (size_t)row * D);

    float4 v[8];
    float s = 0.f, s2 = 0.f;
#pragma unroll
    for (int j = 0; j < 8; j++) {
        float4 f = xr[lane + j * 32];
        v[j] = f;
        s  += f.x + f.y + f.z + f.w;
        s2 += f.x * f.x + f.y * f.y + f.z * f.z + f.w * f.w;
    }
#pragma unroll
    for (int o = 16; o > 0; o >>= 1) {
        s  += __shfl_xor_sync(0xffffffffu, s,  o);
        s2 += __shfl_xor_sync(0xffffffffu, s2, o);
    }
    float mean = s * (1.0f / D);
    float var  = s2 * (1.0f / D) - mean * mean;
    float inv  = rsqrtf(var + 1e-5f);

    uint2* orow = (uint2*)(oh + (size_t)row * D);
    const float4* g4 = (const float4*)gam;
    const float4* b4 = (const float4*)bet;
#pragma unroll
    for (int j = 0; j < 8; j++) {
        int idx = lane + j * 32;
        float4 g = g4[idx], b = b4[idx];
        float r0 = (v[j].x - mean) * inv * g.x + b.x;
        float r1 = (v[j].y - mean) * inv * g.y + b.y;
        float r2 = (v[j].z - mean) * inv * g.z + b.z;
        float r3 = (v[j].w - mean) * inv * g.w + b.w;
        __half2 h0 = __halves2half2(__float2half_rn(r0), __float2half_rn(r1));
        __half2 h1 = __halves2half2(__float2half_rn(r2), __float2half_rn(r3));
        uint2 u;
        u.x = *(uint32_t*)&h0;
        u.y = *(uint32_t*)&h1;
        orow[idx] = u;
    }
}

// ---------------- transpose + convert: W[K,N] fp32 -> T [N,K] fp16 ----------------
__global__ void __launch_bounds__(256) tcvt_kernel(const float* __restrict__ W,
                                                   half* __restrict__ Th,
                                                   int K, int N)
{
    __shared__ float t[32][33];
    int n0 = blockIdx.x * 32, k0 = blockIdx.y * 32;
    int tx = threadIdx.x, ty = threadIdx.y;
#pragma unroll
    for (int j = 0; j < 4; j++)
        t[ty + j * 8][tx] = W[(size_t)(k0 + ty + j * 8) * N + n0 + tx];
    __syncthreads();
#pragma unroll
    for (int j = 0; j < 4; j++) {
        float v = t[tx][ty + j * 8];
        Th[(size_t)(n0 + ty + j * 8) * K + k0 + tx] = __float2half_rn(v);
    }
}

// fused 4x D x D transpose: blockIdx.z selects weight
__global__ void __launch_bounds__(256) tcvt4_kernel(
    const float* __restrict__ W0, half* __restrict__ T0,
    const float* __restrict__ W1, half* __restrict__ T1,
    const float* __restrict__ W2, half* __restrict__ T2,
    const float* __restrict__ W3, half* __restrict__ T3)
{
    const float* W = (blockIdx.z == 0) ? W0 : (blockIdx.z == 1) ? W1 : (blockIdx.z == 2) ? W2 : W3;
    half*       Th = (blockIdx.z == 0) ? T0 : (blockIdx.z == 1) ? T1 : (blockIdx.z == 2) ? T2 : T3;
    __shared__ float t[32][33];
    int n0 = blockIdx.x * 32, k0 = blockIdx.y * 32;
    int tx = threadIdx.x, ty = threadIdx.y;
#pragma unroll
    for (int j = 0; j < 4; j++)
        t[ty + j * 8][tx] = W[(size_t)(k0 + ty + j * 8) * D + n0 + tx];
    __syncthreads();
#pragma unroll
    for (int j = 0; j < 4; j++) {
        float v = t[tx][ty + j * 8];
        Th[(size_t)(n0 + ty + j * 8) * D + k0 + tx] = __float2half_rn(v);
    }
}

// ---------------- fp16 single-pass HMMA GEMM core (f32 acc) ----------------
// C = act(A @ B^T + bias) + res ; A [M,K] fp16, B [N,K] fp16.
// CTA 256x128, 8 warps 64x64, BK=32, 3-stage cp.async pipeline.
// stage: A 256x80B (20480) + B 128x80B (10240) = 30720 B.
#define STG 30720
#define MM_SMEM (3 * STG)

__device__ __forceinline__ void mm_body(
    const half* __restrict__ Ah, const half* __restrict__ Bh,
    const float* __restrict__ bias, const float* __restrict__ res,
    float* __restrict__ Cf, half* __restrict__ Ch,
    int K, int N, int gelu_flag, int bm, int bnc, char* smem)
{
    uint32_t sb = s2u(smem);
    int tid = threadIdx.x, warp = tid >> 5, lane = tid & 31;
    int wm = warp & 3, wn = warp >> 2;
    const int nchunk = K / 32;

    int lr = tid >> 2;          // 0..63
    int cb = (tid & 3) * 16;    // byte chunk in a 64B k-slab

    auto load_stage = [&](int st, int c) {
        uint32_t base = sb + st * STG;
        size_t ko = (size_t)c * 64 + cb;
#pragma unroll
        for (int i = 0; i < 4; i++) {
            int r = lr + i * 64;
            cp16(base + r * 80 + cb, (const char*)Ah + ((size_t)(bm * 256 + r) * K) * 2 + ko);
        }
#pragma unroll
        for (int i = 0; i < 2; i++) {
            int r = lr + i * 64;
            cp16(base + 20480 + r * 80 + cb, (const char*)Bh + ((size_t)(bnc * 128 + r) * K) * 2 + ko);
        }
    };

    float acc[4][8][4];
#pragma unroll
    for (int i = 0; i < 4; i++)
#pragma unroll
        for (int j = 0; j < 8; j++)
#pragma unroll
            for (int r = 0; r < 4; r++) acc[i][j][r] = 0.f;

    load_stage(0, 0); asm volatile("cp.async.commit_group;" ::: "memory");
    load_stage(1, 1); asm volatile("cp.async.commit_group;" ::: "memory");

    int a_row = wm * 64 + (lane & 15);
    int a_kb  = (lane >> 4) * 16;
    int b_row = wn * 64 + (lane & 7) + ((lane >> 4) << 3);
    int b_kb  = ((lane >> 3) & 1) * 16;

    for (int it = 0; it < nchunk; it++) {
        asm volatile("cp.async.wait_group 1;" ::: "memory");
        __syncthreads();
        if (it + 2 < nchunk) load_stage((it + 2) % 3, it + 2);
        asm volatile("cp.async.commit_group;" ::: "memory");

        uint32_t stb = sb + (it % 3) * STG;
#pragma unroll
        for (int ks = 0; ks < 2; ks++) {
            uint32_t aH[4][4];
#pragma unroll
            for (int mt = 0; mt < 4; mt++)
                ldm4(aH[mt], stb + (a_row + mt * 16) * 80 + ks * 32 + a_kb);
#pragma unroll
            for (int np = 0; np < 4; np++) {
                uint32_t bh[4];
                ldm4(bh, stb + 20480 + (b_row + np * 16) * 80 + ks * 32 + b_kb);
#pragma unroll
                for (int mt = 0; mt < 4; mt++) {
                    mma_fp16(acc[mt][np * 2],     aH[mt], bh);
                    mma_fp16(acc[mt][np * 2 + 1], aH[mt], bh + 2);
                }
            }
        }
        __syncthreads();
    }

    // ---- epilogue ----
    int qr = lane >> 2, qc = (lane & 3) * 2;
#pragma unroll
    for (int mt = 0; mt < 4; mt++) {
#pragma unroll
        for (int nt = 0; nt < 8; nt++) {
            int col = bnc * 128 + wn * 64 + nt * 8 + qc;
            float b0 = bias ? bias[col] : 0.f;
            float b1 = bias ? bias[col + 1] : 0.f;
#pragma unroll
            for (int hf = 0; hf < 2; hf++) {
                size_t row = (size_t)bm * 256 + wm * 64 + mt * 16 + qr + hf * 8;
                float v0 = acc[mt][nt][hf * 2]     + b0;
                float v1 = acc[mt][nt][hf * 2 + 1] + b1;
                if (gelu_flag) {
                    v0 = 0.5f * v0 * (1.0f + erff(v0 * 0.70710678118654752f));
                    v1 = 0.5f * v1 * (1.0f + erff(v1 * 0.70710678118654752f));
                }
                size_t idx = row * (size_t)N + col;
                if (res) { v0 += res[idx]; v1 += res[idx + 1]; }
                if (Cf) {
                    *(float2*)(Cf + idx) = make_float2(v0, v1);
                } else {
                    *(__half2*)(Ch + idx) = __halves2half2(__float2half_rn(v0), __float2half_rn(v1));
                }
            }
        }
    }
}

__global__ void __launch_bounds__(256, 1) mm_kernel(
    const half* __restrict__ Ah, const half* __restrict__ Bh,
    const float* __restrict__ bias, const float* __restrict__ res,
    float* __restrict__ Cf, half* __restrict__ Ch,
    int K, int N, int gelu_flag)
{
    extern __shared__ char smem[];
    mm_body(Ah, Bh, bias, res, Cf, Ch, K, N, gelu_flag, blockIdx.y, blockIdx.x, smem);
}

__global__ void __launch_bounds__(256, 1) qkv_kernel(
    const half* __restrict__ Ah,
    const half* __restrict__ Bq, float* __restrict__ Cq,
    const half* __restrict__ Bk, float* __restrict__ Ck,
    const half* __restrict__ Bv, float* __restrict__ Cv)
{
    extern __shared__ char smem[];
    int sel = blockIdx.x >> 3, bnc = blockIdx.x & 7;
    const half* Bh = (sel == 0) ? Bq : (sel == 1) ? Bk : Bv;
    float* Cf      = (sel == 0) ? Cq : (sel == 1) ? Ck : Cv;
    mm_body(Ah, Bh, nullptr, nullptr, Cf, nullptr, D, D, 0, blockIdx.y, bnc, smem);
}

// ---------------- Attention: smem-tiled, 64 queries per CTA; dense row merged ----
// smem layout (bytes): Ks[192*65 f] @0, Vs[195*66 f] @49920, k0s[64] @101408,
// v0s[64] @101664, ps[8][160] @101920. Total 107040.
#define KS_OFF   0
#define VS_OFF   49920
#define K0_OFF   101408
#define V0_OFF   101664
#define PS_OFF   101920
#define ATTN_SMEM 107040

__global__ void __launch_bounds__(256, 1) attn_tile_kernel(
    const float* __restrict__ Q, const float* __restrict__ K,
    const float* __restrict__ V, half* __restrict__ O)
{
    extern __shared__ char smem[];
    int tid = threadIdx.x, warp = tid >> 5, lane = tid & 31;
    int h = blockIdx.y, b = blockIdx.z;
    size_t base = (size_t)b * T * D + h * HD;

    if (blockIdx.x == T / 64) {
        // ---- dense global row i = T-1: 8 warps partition keys, lse merge ----
        const int i = T - 1;
        const float* qp = Q + base + (size_t)i * D;
        float q0 = qp[lane] * 0.125f, q1 = qp[lane + 32] * 0.125f;

        float m = -1e30f, l = 0.f, o0 = 0.f, o1 = 0.f;
        for (int j = warp; j < T; j += 16) {
            const float* kpa = K + base + (size_t)j * D;
            const float* kpb = kpa + (size_t)8 * D;
            float sa = q0 * kpa[lane] + q1 * kpa[lane + 32];
            float sb = q0 * kpb[lane] + q1 * kpb[lane + 32];
#pragma unroll
            for (int o = 16; o > 0; o >>= 1) {
                sa += __shfl_xor_sync(0xffffffffu, sa, o);
                sb += __shfl_xor_sync(0xffffffffu, sb, o);
            }
            float nm = fmaxf(m, fmaxf(sa, sb));
            float scx = __expf(m - nm);
            float pa = __expf(sa - nm);
            float pb = __expf(sb - nm);
            const float* vpa = V + base + (size_t)j * D;
            const float* vpb = vpa + (size_t)8 * D;
            l  = l  * scx + pa + pb;
            o0 = o0 * scx + pa * vpa[lane] + pb * vpb[lane];
            o1 = o1 * scx + pa * vpa[lane + 32] + pb * vpb[lane + 32];
            m = nm;
        }
        float* sm = (float*)smem;               // 8
        float* sl = sm + 8;                     // 8
        float* so = sl + 8;                     // 8*64
        if (lane == 0) { sm[warp] = m; sl[warp] = l; }
        so[warp * 64 + lane] = o0; so[warp * 64 + lane + 32] = o1;
        __syncthreads();
        if (warp == 0) {
            float gm = -1e30f;
#pragma unroll
            for (int w = 0; w < 8; w++) gm = fmaxf(gm, sm[w]);
            float gl = 0.f, a0 = 0.f, a1 = 0.f;
#pragma unroll
            for (int w = 0; w < 8; w++) {
                float scx = __expf(sm[w] - gm);
                gl += scx * sl[w];
                a0 += scx * so[w * 64 + lane];
                a1 += scx * so[w * 64 + lane + 32];
            }
            float inv = 1.f / gl;
            size_t oidx = base + (size_t)i * D;
            O[oidx + lane]      = __float2half_rn(a0 * inv);
            O[oidx + lane + 32] = __float2half_rn(a1 * inv);
        }
        return;
    }

    float* Ks  = (float*)(smem + KS_OFF);   // [r*65 + d]
    float* Vs  = (float*)(smem + VS_OFF);   // [r*66 + d]
    float* k0s = (float*)(smem + K0_OFF);
    float* v0s = (float*)(smem + V0_OFF);
    float* ps  = (float*)(smem + PS_OFF);   // [warp*160 + kk]

    int q0 = blockIdx.x * 64;

    int kLo = q0 - 128; if (kLo < 0) kLo = 0;
    int R = q0 + 64 - kLo;                 // <= 192

    for (int idx = tid; idx < R * 64; idx += 256) {
        int r = idx >> 6, d = idx & 63;
        Ks[r * 65 + d] = K[base + (size_t)(kLo + r) * D + d];
        Vs[r * 66 + d] = V[base + (size_t)(kLo + r) * D + d];
    }
    if (tid < 64) {
        k0s[tid] = K[base + tid];
        v0s[tid] = V[base + tid];
    }
    __syncthreads();

    float* pw = ps + warp * 160;
    int d0 = 2 * lane, d1 = 2 * lane + 1;

    for (int qq = 0; qq < 8; qq++) {
        int i = q0 + warp * 8 + qq;
        if (i == T - 1) continue;   // dense row handled by the extra block

        float qreg[64];
        const float4* qp4 = (const float4*)(Q + base + (size_t)i * D);
#pragma unroll
        for (int t = 0; t < 16; t++) {
            float4 f = qp4[t];
            qreg[4 * t] = f.x; qreg[4 * t + 1] = f.y; qreg[4 * t + 2] = f.z; qreg[4 * t + 3] = f.w;
        }

        int jLo = i - 128; if (jLo < 0) jLo = 0;
        int nk = i - jLo + 1;          // <= 129
        int rBase = jLo - kLo;         // >= 0

        // phase 1: scores (lanes over keys)
        float sc[5];
        float mloc = -1e30f;
#pragma unroll
        for (int bq = 0; bq < 5; bq++) {
            int kk = lane + bq * 32;
            float s = -1e30f;
            if (kk < nk) {
                const float* kr = Ks + (rBase + kk) * 65;
                s = 0.f;
#pragma unroll
                for (int d = 0; d < 64; d++) s += qreg[d] * kr[d];
                s *= 0.125f;
            }
            sc[bq] = s;
            mloc = fmaxf(mloc, s);
        }
        float s0 = -1e30f;
        if (jLo > 0) {                  // global key 0 outside window
            s0 = 0.f;
#pragma unroll
            for (int d = 0; d < 64; d++) s0 += qreg[d] * k0s[d];
            s0 *= 0.125f;
            mloc = fmaxf(mloc, s0);
        }
#pragma unroll
        for (int o = 16; o > 0; o >>= 1) mloc = fmaxf(mloc, __shfl_xor_sync(0xffffffffu, mloc, o));

        float lloc = 0.f;
#pragma unroll
        for (int bq = 0; bq < 5; bq++) {
            float p = __expf(sc[bq] - mloc);
            pw[lane + bq * 32] = p;
            lloc += p;
        }
        float p0 = 0.f;
        if (jLo > 0) {
            p0 = __expf(s0 - mloc);
            if (lane == 0) lloc += p0;
        }
#pragma unroll
        for (int o = 16; o > 0; o >>= 1) lloc += __shfl_xor_sync(0xffffffffu, lloc, o);
        __syncwarp();

        // phase 2: output accumulation, lane owns dims (2*lane, 2*lane+1)
        float o0 = (jLo > 0) ? p0 * v0s[d0] : 0.f;
        float o1 = (jLo > 0) ? p0 * v0s[d1] : 0.f;
        for (int kk = 0; kk < nk; kk += 4) {
            float4 p4 = *(float4*)(pw + kk);
            float pv[4] = {p4.x, p4.y, p4.z, p4.w};
#pragma unroll
            for (int t = 0; t < 4; t++) {
                int r = rBase + kk + t;
                if (r > R - 1) r = R - 1;       // p=0 there; clamp avoids OOB
                float2 v2 = *(float2*)(Vs + r * 66 + d0);
                o0 += pv[t] * v2.x;
                o1 += pv[t] * v2.y;
            }
        }
        float inv = 1.f / lloc;
        *(__half2*)(O + base + (size_t)i * D + d0) =
            __halves2half2(__float2half_rn(o0 * inv), __float2half_rn(o1 * inv));
        __syncwarp();
    }
}

// ---------------- launch ----------------
extern "C" void kernel_launch(void* const* d_in, const int* in_sizes, int n_in,
                              void* d_out, int out_size)
{
    const float* x    = (const float*)d_in[0];
    const float* ln1g = (const float*)d_in[1];
    const float* ln1b = (const float*)d_in[2];
    const float* ln2g = (const float*)d_in[3];
    const float* ln2b = (const float*)d_in[4];
    const float* Wq   = (const float*)d_in[5];
    const float* Wk   = (const float*)d_in[6];
    const float* Wv   = (const float*)d_in[7];
    const float* Wo   = (const float*)d_in[8];
    const float* bo   = (const float*)d_in[9];
    const float* W1   = (const float*)d_in[10];
    const float* b1   = (const float*)d_in[11];
    const float* W2   = (const float*)d_in[12];
    const float* b2   = (const float*)d_in[13];
    float* out = (float*)d_out;

    cudaFuncSetAttribute(mm_kernel,  cudaFuncAttributeMaxDynamicSharedMemorySize, MM_SMEM);
    cudaFuncSetAttribute(qkv_kernel, cudaFuncAttributeMaxDynamicSharedMemorySize, MM_SMEM);
    cudaFuncSetAttribute(attn_tile_kernel, cudaFuncAttributeMaxDynamicSharedMemorySize, ATTN_SMEM);

    float *q, *k, *v, *x2;
    half *hA, *aA, *h2A, *f1A;
    half *WqT, *WkT, *WvT, *WoT, *W1T, *W2T;
    cudaGetSymbolAddress((void**)&q,   g_q);
    cudaGetSymbolAddress((void**)&k,   g_k);
    cudaGetSymbolAddress((void**)&v,   g_v);
    cudaGetSymbolAddress((void**)&x2,  g_x2);
    cudaGetSymbolAddress((void**)&hA,  g_h);
    cudaGetSymbolAddress((void**)&aA,  g_a);
    cudaGetSymbolAddress((void**)&h2A, g_h2);
    cudaGetSymbolAddress((void**)&f1A, g_f1);
    cudaGetSymbolAddress((void**)&WqT, g_WqT);
    cudaGetSymbolAddress((void**)&WkT, g_WkT);
    cudaGetSymbolAddress((void**)&WvT, g_WvT);
    cudaGetSymbolAddress((void**)&WoT, g_WoT);
    cudaGetSymbolAddress((void**)&W1T, g_W1T);
    cudaGetSymbolAddress((void**)&W2T, g_W2T);

    dim3 tb(32, 8);
    tcvt4_kernel<<<dim3(D / 32, D / 32, 4), tb>>>(Wq, WqT, Wk, WkT, Wv, WvT, Wo, WoT);
    tcvt_kernel<<<dim3(DFF / 32, D / 32), tb>>>(W1, W1T, D, DFF);
    tcvt_kernel<<<dim3(D / 32, DFF / 32), tb>>>(W2, W2T, DFF, D);

    // 1. h = LN1(x)
    ln_kernel<<<NT / 8, 256>>>(x, ln1g, ln1b, hA);

    // 2. fused QKV (fp32 out)
    qkv_kernel<<<dim3(24, NT / 256), 256, MM_SMEM>>>(hA, WqT, q, WkT, k, WvT, v);

    // 3. attention (dense row merged as extra grid column)
    attn_tile_kernel<<<dim3(T / 64 + 1, NH, Bsz), 256, ATTN_SMEM>>>(q, k, v, aA);

    // 4. x2 = x + att @ Wo + bo
    dim3 gD(D / 128, NT / 256);
    mm_kernel<<<gD, 256, MM_SMEM>>>(aA, WoT, bo, x, x2, nullptr, D, D, 0);

    // 5. h2 = LN2(x2)
    ln_kernel<<<NT / 8, 256>>>(x2, ln2g, ln2b, h2A);

    // 6. f1 = gelu(h2 @ W1 + b1)
    dim3 gF(DFF / 128, NT / 256);
    mm_kernel<<<gF, 256, MM_SMEM>>>(h2A, W1T, b1, nullptr, nullptr, f1A, D, DFF, 1);

    // 7. out = x2 + f1 @ W2 + b2
    mm_kernel<<<gD, 256, MM_SMEM>>>(f1A, W2T, b2, x2, out, nullptr, DFF, D, 0);
}

// round 17
// speedup vs baseline: 1.1966x; 1.0124x over previous
#include <cuda_runtime.h>
#include <cuda_fp16.h>
#include <math.h>
#include <stdint.h>

#define Bsz 2
#define T 2048
#define D 1024
#define NH 16
#define HD 64
#define NT (Bsz*T)    /* 4096 rows */
#define DFF 4096

// ---------------- scratch ----------------
__device__ float g_q [NT*D];
__device__ float g_k [NT*D];
__device__ float g_v [NT*D];
__device__ float g_x2[NT*D];

__device__ half g_h  [NT*D];          // LN1 out
__device__ half g_a  [NT*D];          // attention out
__device__ half g_h2 [NT*D];          // LN2 out
__device__ half g_f1 [(size_t)NT*DFF];// FFN mid

__device__ half g_WqT[D*D];
__device__ half g_WkT[D*D];
__device__ half g_WvT[D*D];
__device__ half g_WoT[D*D];
__device__ half g_W1T[(size_t)D*DFF];   // [DFF, D]
__device__ half g_W2T[(size_t)D*DFF];   // [D, DFF]

// ---------------- helpers ----------------
__device__ __forceinline__ uint32_t s2u(const void* p) {
    uint32_t a;
    asm("{ .reg .u64 t; cvta.to.shared.u64 t, %1; cvt.u32.u64 %0, t; }" : "=r"(a) : "l"(p));
    return a;
}
__device__ __forceinline__ void cp16(uint32_t d, const void* s) {
    asm volatile("cp.async.cg.shared.global [%0], [%1], 16;" :: "r"(d), "l"(s));
}
__device__ __forceinline__ void ldm4(uint32_t* r, uint32_t addr) {
    asm volatile("ldmatrix.sync.aligned.m8n8.x4.shared.b16 {%0,%1,%2,%3}, [%4];"
        : "=r"(r[0]), "=r"(r[1]), "=r"(r[2]), "=r"(r[3]) : "r"(addr));
}
__device__ __forceinline__ void mma_fp16(float* d, const uint32_t* a, const uint32_t* b) {
    asm volatile("mma.sync.aligned.m16n8k16.row.col.f32.f16.f16.f32 "
        "{%0,%1,%2,%3}, {%4,%5,%6,%7}, {%8,%9}, {%0,%1,%2,%3};"
        : "+f"(d[0]), "+f"(d[1]), "+f"(d[2]), "+f"(d[3])
        : "r"(a[0]), "r"(a[1]), "r"(a[2]), "r"(a[3]), "r"(b[0]), "r"(b[1]));
}

// ---------------- LayerNorm: warp per row, float4, no block sync ----------------
__global__ void __launch_bounds__(256) ln_kernel(const float* __restrict__ x,
                                                 const float* __restrict__ gam,
                                                 const float* __restrict__ bet,
                                                 half* __restrict__ oh)
{
    int warp = threadIdx.x >> 5, lane = threadIdx.x & 31;
    int row = blockIdx.x * 8 + warp;
    const float4* xr = (const float4*)(x + (size_t)row * D);

    float4 v[8];
    float s = 0.f, s2 = 0.f;
#pragma unroll
    for (int j = 0; j < 8; j++) {
        float4 f = xr[lane + j * 32];
        v[j] = f;
        s  += f.x + f.y + f.z + f.w;
        s2 += f.x * f.x + f.y * f.y + f.z * f.z + f.w * f.w;
    }
#pragma unroll
    for (int o = 16; o > 0; o >>= 1) {
        s  += __shfl_xor_sync(0xffffffffu, s,  o);
        s2 += __shfl_xor_sync(0xffffffffu, s2, o);
    }
    float mean = s * (1.0f / D);
    float var  = s2 * (1.0f / D) - mean * mean;
    float inv  = rsqrtf(var + 1e-5f);

    uint2* orow = (uint2*)(oh + (size_t)row * D);
    const float4* g4 = (const float4*)gam;
    const float4* b4 = (const float4*)bet;
#pragma unroll
    for (int j = 0; j < 8; j++) {
        int idx = lane + j * 32;
        float4 g = g4[idx], b = b4[idx];
        float r0 = (v[j].x - mean) * inv * g.x + b.x;
        float r1 = (v[j].y - mean) * inv * g.y + b.y;
        float r2 = (v[j].z - mean) * inv * g.z + b.z;
        float r3 = (v[j].w - mean) * inv * g.w + b.w;
        __half2 h0 = __halves2half2(__float2half_rn(r0), __float2half_rn(r1));
        __half2 h1 = __halves2half2(__float2half_rn(r2), __float2half_rn(r3));
        uint2 u;
        u.x = *(uint32_t*)&h0;
        u.y = *(uint32_t*)&h1;
        orow[idx] = u;
    }
}

// fused 4x D x D transpose: blockIdx.z selects weight
__global__ void __launch_bounds__(256) tcvt4_kernel(
    const float* __restrict__ W0, half* __restrict__ T0,
    const float* __restrict__ W1, half* __restrict__ T1,
    const float* __restrict__ W2, half* __restrict__ T2,
    const float* __restrict__ W3, half* __restrict__ T3)
{
    const float* W = (blockIdx.z == 0) ? W0 : (blockIdx.z == 1) ? W1 : (blockIdx.z == 2) ? W2 : W3;
    half*       Th = (blockIdx.z == 0) ? T0 : (blockIdx.z == 1) ? T1 : (blockIdx.z == 2) ? T2 : T3;
    __shared__ float t[32][33];
    int n0 = blockIdx.x * 32, k0 = blockIdx.y * 32;
    int tx = threadIdx.x, ty = threadIdx.y;
#pragma unroll
    for (int j = 0; j < 4; j++)
        t[ty + j * 8][tx] = W[(size_t)(k0 + ty + j * 8) * D + n0 + tx];
    __syncthreads();
#pragma unroll
    for (int j = 0; j < 4; j++) {
        float v = t[tx][ty + j * 8];
        Th[(size_t)(n0 + ty + j * 8) * D + k0 + tx] = __float2half_rn(v);
    }
}

// fused W1 [D,DFF] + W2 [DFF,D] transpose: z=0 -> W1, z=1 -> W2 (roles swapped)
__global__ void __launch_bounds__(256) tcvtff_kernel(
    const float* __restrict__ W1, half* __restrict__ T1,
    const float* __restrict__ W2, half* __restrict__ T2)
{
    __shared__ float t[32][33];
    int tx = threadIdx.x, ty = threadIdx.y;
    const float* W; half* Th; int K, N, n0, k0;
    if (blockIdx.z == 0) { W = W1; Th = T1; K = D;   N = DFF; n0 = blockIdx.x * 32; k0 = blockIdx.y * 32; }
    else                 { W = W2; Th = T2; K = DFF; N = D;   n0 = blockIdx.y * 32; k0 = blockIdx.x * 32; }
#pragma unroll
    for (int j = 0; j < 4; j++)
        t[ty + j * 8][tx] = W[(size_t)(k0 + ty + j * 8) * N + n0 + tx];
    __syncthreads();
#pragma unroll
    for (int j = 0; j < 4; j++) {
        float v = t[tx][ty + j * 8];
        Th[(size_t)(n0 + ty + j * 8) * K + k0 + tx] = __float2half_rn(v);
    }
}

// ---------------- fp16 single-pass HMMA GEMM core (f32 acc) ----------------
// C = act(A @ B^T + bias) + res ; A [M,K] fp16, B [N,K] fp16.
// CTA 256x128, 8 warps 64x64, BK=32, 3-stage cp.async pipeline.
#define STG 30720
#define MM_SMEM (3 * STG)

__device__ __forceinline__ void mm_body(
    const half* __restrict__ Ah, const half* __restrict__ Bh,
    const float* __restrict__ bias, const float* __restrict__ res,
    float* __restrict__ Cf, half* __restrict__ Ch,
    int K, int N, int gelu_flag, int bm, int bnc, char* smem)
{
    uint32_t sb = s2u(smem);
    int tid = threadIdx.x, warp = tid >> 5, lane = tid & 31;
    int wm = warp & 3, wn = warp >> 2;
    const int nchunk = K / 32;

    int lr = tid >> 2;          // 0..63
    int cb = (tid & 3) * 16;    // byte chunk in a 64B k-slab

    auto load_stage = [&](int st, int c) {
        uint32_t base = sb + st * STG;
        size_t ko = (size_t)c * 64 + cb;
#pragma unroll
        for (int i = 0; i < 4; i++) {
            int r = lr + i * 64;
            cp16(base + r * 80 + cb, (const char*)Ah + ((size_t)(bm * 256 + r) * K) * 2 + ko);
        }
#pragma unroll
        for (int i = 0; i < 2; i++) {
            int r = lr + i * 64;
            cp16(base + 20480 + r * 80 + cb, (const char*)Bh + ((size_t)(bnc * 128 + r) * K) * 2 + ko);
        }
    };

    float acc[4][8][4];
#pragma unroll
    for (int i = 0; i < 4; i++)
#pragma unroll
        for (int j = 0; j < 8; j++)
#pragma unroll
            for (int r = 0; r < 4; r++) acc[i][j][r] = 0.f;

    load_stage(0, 0); asm volatile("cp.async.commit_group;" ::: "memory");
    load_stage(1, 1); asm volatile("cp.async.commit_group;" ::: "memory");

    int a_row = wm * 64 + (lane & 15);
    int a_kb  = (lane >> 4) * 16;
    int b_row = wn * 64 + (lane & 7) + ((lane >> 4) << 3);
    int b_kb  = ((lane >> 3) & 1) * 16;

    for (int it = 0; it < nchunk; it++) {
        asm volatile("cp.async.wait_group 1;" ::: "memory");
        __syncthreads();
        if (it + 2 < nchunk) load_stage((it + 2) % 3, it + 2);
        asm volatile("cp.async.commit_group;" ::: "memory");

        uint32_t stb = sb + (it % 3) * STG;
#pragma unroll
        for (int ks = 0; ks < 2; ks++) {
            uint32_t aH[4][4];
#pragma unroll
            for (int mt = 0; mt < 4; mt++)
                ldm4(aH[mt], stb + (a_row + mt * 16) * 80 + ks * 32 + a_kb);
#pragma unroll
            for (int np = 0; np < 4; np++) {
                uint32_t bh[4];
                ldm4(bh, stb + 20480 + (b_row + np * 16) * 80 + ks * 32 + b_kb);
#pragma unroll
                for (int mt = 0; mt < 4; mt++) {
                    mma_fp16(acc[mt][np * 2],     aH[mt], bh);
                    mma_fp16(acc[mt][np * 2 + 1], aH[mt], bh + 2);
                }
            }
        }
        __syncthreads();
    }

    // ---- epilogue ----
    int qr = lane >> 2, qc = (lane & 3) * 2;
#pragma unroll
    for (int mt = 0; mt < 4; mt++) {
#pragma unroll
        for (int nt = 0; nt < 8; nt++) {
            int col = bnc * 128 + wn * 64 + nt * 8 + qc;
            float b0 = bias ? bias[col] : 0.f;
            float b1 = bias ? bias[col + 1] : 0.f;
#pragma unroll
            for (int hf = 0; hf < 2; hf++) {
                size_t row = (size_t)bm * 256 + wm * 64 + mt * 16 + qr + hf * 8;
                float v0 = acc[mt][nt][hf * 2]     + b0;
                float v1 = acc[mt][nt][hf * 2 + 1] + b1;
                if (gelu_flag) {
                    v0 = 0.5f * v0 * (1.0f + erff(v0 * 0.70710678118654752f));
                    v1 = 0.5f * v1 * (1.0f + erff(v1 * 0.70710678118654752f));
                }
                size_t idx = row * (size_t)N + col;
                if (res) { v0 += res[idx]; v1 += res[idx + 1]; }
                if (Cf) {
                    *(float2*)(Cf + idx) = make_float2(v0, v1);
                } else {
                    *(__half2*)(Ch + idx) = __halves2half2(__float2half_rn(v0), __float2half_rn(v1));
                }
            }
        }
    }
}

__global__ void __launch_bounds__(256, 1) mm_kernel(
    const half* __restrict__ Ah, const half* __restrict__ Bh,
    const float* __restrict__ bias, const float* __restrict__ res,
    float* __restrict__ Cf, half* __restrict__ Ch,
    int K, int N, int gelu_flag)
{
    extern __shared__ char smem[];
    mm_body(Ah, Bh, bias, res, Cf, Ch, K, N, gelu_flag, blockIdx.y, blockIdx.x, smem);
}

__global__ void __launch_bounds__(256, 1) qkv_kernel(
    const half* __restrict__ Ah,
    const half* __restrict__ Bq, float* __restrict__ Cq,
    const half* __restrict__ Bk, float* __restrict__ Ck,
    const half* __restrict__ Bv, float* __restrict__ Cv)
{
    extern __shared__ char smem[];
    int sel = blockIdx.x >> 3, bnc = blockIdx.x & 7;
    const half* Bh = (sel == 0) ? Bq : (sel == 1) ? Bk : Bv;
    float* Cf      = (sel == 0) ? Cq : (sel == 1) ? Ck : Cv;
    mm_body(Ah, Bh, nullptr, nullptr, Cf, nullptr, D, D, 0, blockIdx.y, bnc, smem);
}

// ---------------- Attention: half2 smem tiles, 64 queries per CTA; dense row merged
// smem (bytes): Ks half2[192][33] @0 (25344), Vs @25344, k0s @50688 (128),
// v0s @50816 (128), ps float[8][160] @50944 (5120). Total 56064.
#define KS_OFF   0
#define VS_OFF   25344
#define K0_OFF   50688
#define V0_OFF   50816
#define PS_OFF   50944
#define ATTN_SMEM 56064

__global__ void __launch_bounds__(256) attn_tile_kernel(
    const float* __restrict__ Q, const float* __restrict__ K,
    const float* __restrict__ V, half* __restrict__ O)
{
    extern __shared__ char smem[];
    int tid = threadIdx.x, warp = tid >> 5, lane = tid & 31;
    int h = blockIdx.y, b = blockIdx.z;
    size_t base = (size_t)b * T * D + h * HD;

    if (blockIdx.x == T / 64) {
        // ---- dense global row i = T-1: 8 warps partition keys, lse merge ----
        const int i = T - 1;
        const float* qp = Q + base + (size_t)i * D;
        float q0 = qp[lane] * 0.125f, q1 = qp[lane + 32] * 0.125f;

        float m = -1e30f, l = 0.f, o0 = 0.f, o1 = 0.f;
        for (int j = warp; j < T; j += 16) {
            const float* kpa = K + base + (size_t)j * D;
            const float* kpb = kpa + (size_t)8 * D;
            float sa = q0 * kpa[lane] + q1 * kpa[lane + 32];
            float sb = q0 * kpb[lane] + q1 * kpb[lane + 32];
#pragma unroll
            for (int o = 16; o > 0; o >>= 1) {
                sa += __shfl_xor_sync(0xffffffffu, sa, o);
                sb += __shfl_xor_sync(0xffffffffu, sb, o);
            }
            float nm = fmaxf(m, fmaxf(sa, sb));
            float scx = __expf(m - nm);
            float pa = __expf(sa - nm);
            float pb = __expf(sb - nm);
            const float* vpa = V + base + (size_t)j * D;
            const float* vpb = vpa + (size_t)8 * D;
            l  = l  * scx + pa + pb;
            o0 = o0 * scx + pa * vpa[lane] + pb * vpb[lane];
            o1 = o1 * scx + pa * vpa[lane + 32] + pb * vpb[lane + 32];
            m = nm;
        }
        float* sm = (float*)smem;               // 8
        float* sl = sm + 8;                     // 8
        float* so = sl + 8;                     // 8*64
        if (lane == 0) { sm[warp] = m; sl[warp] = l; }
        so[warp * 64 + lane] = o0; so[warp * 64 + lane + 32] = o1;
        __syncthreads();
        if (warp == 0) {
            float gm = -1e30f;
#pragma unroll
            for (int w = 0; w < 8; w++) gm = fmaxf(gm, sm[w]);
            float gl = 0.f, a0 = 0.f, a1 = 0.f;
#pragma unroll
            for (int w = 0; w < 8; w++) {
                float scx = __expf(sm[w] - gm);
                gl += scx * sl[w];
                a0 += scx * so[w * 64 + lane];
                a1 += scx * so[w * 64 + lane + 32];
            }
            float inv = 1.f / gl;
            size_t oidx = base + (size_t)i * D;
            O[oidx + lane]      = __float2half_rn(a0 * inv);
            O[oidx + lane + 32] = __float2half_rn(a1 * inv);
        }
        return;
    }

    __half2* Ks  = (__half2*)(smem + KS_OFF);   // [r*33 + d2]
    __half2* Vs  = (__half2*)(smem + VS_OFF);
    __half2* k0s = (__half2*)(smem + K0_OFF);
    __half2* v0s = (__half2*)(smem + V0_OFF);
    float*   ps  = (float*)(smem + PS_OFF);     // [warp*160 + kk]

    int q0 = blockIdx.x * 64;
    int kLo = q0 - 128; if (kLo < 0) kLo = 0;
    int R = q0 + 64 - kLo;                 // <= 192

    for (int idx = tid; idx < R * 32; idx += 256) {
        int r = idx >> 5, d = idx & 31;
        float2 kf = ((const float2*)(K + base + (size_t)(kLo + r) * D))[d];
        float2 vf = ((const float2*)(V + base + (size_t)(kLo + r) * D))[d];
        Ks[r * 33 + d] = __float22half2_rn(kf);
        Vs[r * 33 + d] = __float22half2_rn(vf);
    }
    if (tid < 32) {
        k0s[tid] = __float22half2_rn(((const float2*)(K + base))[tid]);
        v0s[tid] = __float22half2_rn(((const float2*)(V + base))[tid]);
    }
    __syncthreads();

    float* pw = ps + warp * 160;

    for (int qq = 0; qq < 8; qq++) {
        int i = q0 + warp * 8 + qq;
        if (i == T - 1) continue;   // dense row handled by the extra block

        float qreg[64];
        const float4* qp4 = (const float4*)(Q + base + (size_t)i * D);
#pragma unroll
        for (int t = 0; t < 16; t++) {
            float4 f = qp4[t];
            qreg[4 * t] = f.x; qreg[4 * t + 1] = f.y; qreg[4 * t + 2] = f.z; qreg[4 * t + 3] = f.w;
        }

        int jLo = i - 128; if (jLo < 0) jLo = 0;
        int nk = i - jLo + 1;          // <= 129
        int rBase = jLo - kLo;         // >= 0

        // phase 1: scores (lanes over keys), half2 K + fp32 accumulate
        float sc[5];
        float mloc = -1e30f;
#pragma unroll
        for (int bq = 0; bq < 5; bq++) {
            int kk = lane + bq * 32;
            float s = -1e30f;
            if (kk < nk) {
                const __half2* kr = Ks + (rBase + kk) * 33;
                s = 0.f;
#pragma unroll
                for (int d = 0; d < 32; d++) {
                    float2 kv = __half22float2(kr[d]);
                    s += qreg[2 * d] * kv.x + qreg[2 * d + 1] * kv.y;
                }
                s *= 0.125f;
            }
            sc[bq] = s;
            mloc = fmaxf(mloc, s);
        }
        float s0 = -1e30f;
        if (jLo > 0) {                  // global key 0 outside window
            s0 = 0.f;
#pragma unroll
            for (int d = 0; d < 32; d++) {
                float2 kv = __half22float2(k0s[d]);
                s0 += qreg[2 * d] * kv.x + qreg[2 * d + 1] * kv.y;
            }
            s0 *= 0.125f;
            mloc = fmaxf(mloc, s0);
        }
#pragma unroll
        for (int o = 16; o > 0; o >>= 1) mloc = fmaxf(mloc, __shfl_xor_sync(0xffffffffu, mloc, o));

        float lloc = 0.f;
#pragma unroll
        for (int bq = 0; bq < 5; bq++) {
            float p = __expf(sc[bq] - mloc);
            pw[lane + bq * 32] = p;
            lloc += p;
        }
        float p0 = 0.f;
        if (jLo > 0) {
            p0 = __expf(s0 - mloc);
            if (lane == 0) lloc += p0;
        }
#pragma unroll
        for (int o = 16; o > 0; o >>= 1) lloc += __shfl_xor_sync(0xffffffffu, lloc, o);
        __syncwarp();

        // phase 2: output accumulation, lane owns dims (2*lane, 2*lane+1)
        float2 v0p = __half22float2(v0s[lane]);
        float o0 = (jLo > 0) ? p0 * v0p.x : 0.f;
        float o1 = (jLo > 0) ? p0 * v0p.y : 0.f;
        for (int kk = 0; kk < nk; kk += 4) {
            float4 p4 = *(float4*)(pw + kk);
            float pv[4] = {p4.x, p4.y, p4.z, p4.w};
#pragma unroll
            for (int t = 0; t < 4; t++) {
                int r = rBase + kk + t;
                if (r > R - 1) r = R - 1;       // p=0 there; clamp avoids OOB
                float2 v2 = __half22float2(Vs[r * 33 + lane]);
                o0 += pv[t] * v2.x;
                o1 += pv[t] * v2.y;
            }
        }
        float inv = 1.f / lloc;
        *(__half2*)(O + base + (size_t)i * D + 2 * lane) =
            __halves2half2(__float2half_rn(o0 * inv), __float2half_rn(o1 * inv));
        __syncwarp();
    }
}

// ---------------- launch ----------------
extern "C" void kernel_launch(void* const* d_in, const int* in_sizes, int n_in,
                              void* d_out, int out_size)
{
    const float* x    = (const float*)d_in[0];
    const float* ln1g = (const float*)d_in[1];
    const float* ln1b = (const float*)d_in[2];
    const float* ln2g = (const float*)d_in[3];
    const float* ln2b = (const float*)d_in[4];
    const float* Wq   = (const float*)d_in[5];
    const float* Wk   = (const float*)d_in[6];
    const float* Wv   = (const float*)d_in[7];
    const float* Wo   = (const float*)d_in[8];
    const float* bo   = (const float*)d_in[9];
    const float* W1   = (const float*)d_in[10];
    const float* b1   = (const float*)d_in[11];
    const float* W2   = (const float*)d_in[12];
    const float* b2   = (const float*)d_in[13];
    float* out = (float*)d_out;

    cudaFuncSetAttribute(mm_kernel,  cudaFuncAttributeMaxDynamicSharedMemorySize, MM_SMEM);
    cudaFuncSetAttribute(qkv_kernel, cudaFuncAttributeMaxDynamicSharedMemorySize, MM_SMEM);
    cudaFuncSetAttribute(attn_tile_kernel, cudaFuncAttributeMaxDynamicSharedMemorySize, ATTN_SMEM);

    float *q, *k, *v, *x2;
    half *hA, *aA, *h2A, *f1A;
    half *WqT, *WkT, *WvT, *WoT, *W1T, *W2T;
    cudaGetSymbolAddress((void**)&q,   g_q);
    cudaGetSymbolAddress((void**)&k,   g_k);
    cudaGetSymbolAddress((void**)&v,   g_v);
    cudaGetSymbolAddress((void**)&x2,  g_x2);
    cudaGetSymbolAddress((void**)&hA,  g_h);
    cudaGetSymbolAddress((void**)&aA,  g_a);
    cudaGetSymbolAddress((void**)&h2A, g_h2);
    cudaGetSymbolAddress((void**)&f1A, g_f1);
    cudaGetSymbolAddress((void**)&WqT, g_WqT);
    cudaGetSymbolAddress((void**)&WkT, g_WkT);
    cudaGetSymbolAddress((void**)&WvT, g_WvT);
    cudaGetSymbolAddress((void**)&WoT, g_WoT);
    cudaGetSymbolAddress((void**)&W1T, g_W1T);
    cudaGetSymbolAddress((void**)&W2T, g_W2T);

    dim3 tb(32, 8);
    tcvt4_kernel<<<dim3(D / 32, D / 32, 4), tb>>>(Wq, WqT, Wk, WkT, Wv, WvT, Wo, WoT);
    tcvtff_kernel<<<dim3(DFF / 32, D / 32, 2), tb>>>(W1, W1T, W2, W2T);

    // 1. h = LN1(x)
    ln_kernel<<<NT / 8, 256>>>(x, ln1g, ln1b, hA);

    // 2. fused QKV (fp32 out)
    qkv_kernel<<<dim3(24, NT / 256), 256, MM_SMEM>>>(hA, WqT, q, WkT, k, WvT, v);

    // 3. attention (dense row merged as extra grid column)
    attn_tile_kernel<<<dim3(T / 64 + 1, NH, Bsz), 256, ATTN_SMEM>>>(q, k, v, aA);

    // 4. x2 = x + att @ Wo + bo
    dim3 gD(D / 128, NT / 256);
    mm_kernel<<<gD, 256, MM_SMEM>>>(aA, WoT, bo, x, x2, nullptr, D, D, 0);

    // 5. h2 = LN2(x2)
    ln_kernel<<<NT / 8, 256>>>(x2, ln2g, ln2b, h2A);

    // 6. f1 = gelu(h2 @ W1 + b1)
    dim3 gF(DFF / 128, NT / 256);
    mm_kernel<<<gF, 256, MM_SMEM>>>(h2A, W1T, b1, nullptr, nullptr, f1A, D, DFF, 1);

    // 7. out = x2 + f1 @ W2 + b2
    mm_kernel<<<gD, 256, MM_SMEM>>>(f1A, W2T, b2, x2, out, nullptr, DFF, D, 0);
}